// round 10
// baseline (speedup 1.0000x reference)
#include <cuda_runtime.h>
#include <cuda_bf16.h>

#define BATCH  4
#define SEQ    2048
#define DMODEL 1024
#define NSTATE 16
#define SEG    32                  // segment length
#define NSEGS  (SEQ / SEG)         // 64 segments
#define NCH    (BATCH * DMODEL)    // 4096 channels
#define GRID   592                 // 4 blocks/SM x 148 (GB300 has 152 SMs -> margin)
#define NT     256

typedef unsigned long long ull;

// packed f32x2 helpers (true fp32 lanes — no precision loss)
__device__ __forceinline__ ull pack2(float lo, float hi) {
    ull r; asm("mov.b64 %0, {%1, %2};" : "=l"(r) : "f"(lo), "f"(hi)); return r;
}
__device__ __forceinline__ void fma2(ull& d, ull a, ull b) {
    asm("fma.rn.f32x2 %0, %1, %2, %0;" : "+l"(d) : "l"(a), "l"(b));
}
__device__ __forceinline__ float unpack_add(ull p) {
    float lo, hi; asm("mov.b64 {%0, %1}, %2;" : "=f"(lo), "=f"(hi) : "l"(p));
    return lo + hi;
}

// ---------------- device scratch (static: no allocation) ----------------
__device__ float  g_c[SEG];                   // c_k = b^T A^k b
__device__ float4 g_vrev4[SEG][4];            // vrev[s] = A^{SEG-1-s} b
__device__ float4 g_Q4[SEG][4];               // Q[r]  = b^T A^{r+1}
__device__ float  g_A32[NSTATE * NSTATE];     // A^SEG
__device__ float4 g_V4[NSEGS * NCH * 4];      // injected state [g][ch][16]  (16.8 MB)
__device__ float4 g_H4[NSEGS * NCH * 4];      // entry states   [g][ch][16]  (16.8 MB)
__device__ unsigned g_cnt[4];                 // barrier arrival counters (zero-init)
__device__ unsigned g_flag[4];                // barrier release flags (monotone)

// sense-reversing software grid barrier; safe across graph replays
// (snapshot-before-arrive; counter reset by releaser before flag bump)
__device__ __forceinline__ void grid_barrier(int i) {
    __threadfence();                          // publish this thread's writes
    __syncthreads();
    if (threadIdx.x == 0) {
        volatile unsigned* flag = &g_flag[i];
        const unsigned snap = *flag;
        const unsigned old = atomicAdd(&g_cnt[i], 1u);
        if (old == GRID - 1) {
            atomicExch(&g_cnt[i], 0u);
            __threadfence();
            atomicAdd(&g_flag[i], 1u);
        } else {
            while (*flag == snap) __nanosleep(64);
        }
        __threadfence();
    }
    __syncthreads();
}

extern "C" __global__ void __launch_bounds__(NT, 4)
fused_all(const float* __restrict__ x, const float* __restrict__ A,
          const float* __restrict__ bv, float* __restrict__ out) {
    __shared__ union SmemU {
        struct { float sA[256]; float M[2][256]; float sb[16]; } p0;       // k0 scratch
        struct { ulonglong2 sv2[SEG][4]; } p1;                             // vrev packed
        struct { float sx[SEG][256]; float sc[SEG]; ulonglong2 sQp[SEG][4]; } p3; // 33 KB
    } sm;
    const int tid = threadIdx.x;
    const int bid = blockIdx.x;

    // ================= PHASE 0: block 0 precompute; others prefetch x to L2 ========
    if (bid == 0) {
        sm.p0.sA[tid] = A[tid];
        if (tid < NSTATE) sm.p0.sb[tid] = bv[tid];
        sm.p0.M[0][tid] = ((tid >> 4) == (tid & 15)) ? 1.f : 0.f;   // M = I
        __syncthreads();

        float* vrev = (float*)g_vrev4;
        float* Q    = (float*)g_Q4;
        int cur = 0;
        const int row = tid >> 4, col = tid & 15;
        for (int j = 0; j < SEG; ++j) {         // loop top: M[cur] = A^j
            if (tid < NSTATE) {                 // vrev[SEG-1-j] = A^j b
                float a = 0.f;
                #pragma unroll
                for (int n = 0; n < NSTATE; ++n)
                    a = fmaf(sm.p0.M[cur][tid * NSTATE + n], sm.p0.sb[n], a);
                vrev[(SEG - 1 - j) * NSTATE + tid] = a;
            } else if (tid < 32 && j >= 1) {    // Q[j-1] = b^T A^j
                const int m = tid - NSTATE;
                float a = 0.f;
                #pragma unroll
                for (int k = 0; k < NSTATE; ++k)
                    a = fmaf(sm.p0.sb[k], sm.p0.M[cur][k * NSTATE + m], a);
                Q[(j - 1) * NSTATE + m] = a;
            }
            float a = 0.f;                      // M[1-cur] = M[cur] * A
            #pragma unroll
            for (int k = 0; k < NSTATE; ++k)
                a = fmaf(sm.p0.M[cur][row * NSTATE + k], sm.p0.sA[k * NSTATE + col], a);
            sm.p0.M[1 - cur][tid] = a;
            __syncthreads();
            cur ^= 1;
        }
        g_A32[tid] = sm.p0.M[cur][tid];
        if (tid < NSTATE) {                     // Q[SEG-1] = b^T A^SEG
            float a = 0.f;
            #pragma unroll
            for (int k = 0; k < NSTATE; ++k)
                a = fmaf(sm.p0.sb[k], sm.p0.M[cur][k * NSTATE + tid], a);
            Q[(SEG - 1) * NSTATE + tid] = a;
        }
        if (tid < SEG) {                        // c_k = b . A^k b
            float a = 0.f;
            #pragma unroll
            for (int m = 0; m < NSTATE; ++m)
                a = fmaf(sm.p0.sb[m], vrev[(SEG - 1 - tid) * NSTATE + m], a);
            g_c[tid] = a;
        }
    } else {
        // warm L2 with x while block 0 computes taps (hides phase-0 serial time)
        for (int job = bid; job < NCH * NSEGS / NT; job += GRID) {
            const int dt = job & 3, b = (job >> 2) & 3, g = job >> 4;
            const float* xp = x + ((size_t)(b * SEQ + g * SEG)) * DMODEL + dt * 256 + tid;
            #pragma unroll
            for (int s = 0; s < SEG; ++s)
                asm volatile("prefetch.global.L2 [%0];" :: "l"(xp + (size_t)s * DMODEL));
        }
    }
    grid_barrier(0);

    // ================= PHASE 1: injected state  V = sum_s A^{SEG-1-s} b x_s ========
    if (tid < SEG * 4) ((ulonglong2*)sm.p1.sv2)[tid] = ((const ulonglong2*)g_vrev4)[tid];
    __syncthreads();
    for (int job = bid; job < NCH * NSEGS / NT; job += GRID) {   // 1024 jobs
        const int dt = job & 3, b = (job >> 2) & 3, g = job >> 4;
        const int d = dt * 256 + tid;
        const float* xp = x + ((size_t)(b * SEQ + g * SEG)) * DMODEL + d;
        ull V2[8];
        #pragma unroll
        for (int j = 0; j < 8; ++j) V2[j] = 0ull;
        #pragma unroll
        for (int s = 0; s < SEG; ++s) {
            const float xv  = xp[(size_t)s * DMODEL];
            const ull   xv2 = pack2(xv, xv);
            const ulonglong2 w0 = sm.p1.sv2[s][0], w1 = sm.p1.sv2[s][1];
            const ulonglong2 w2 = sm.p1.sv2[s][2], w3 = sm.p1.sv2[s][3];
            fma2(V2[0], w0.x, xv2); fma2(V2[1], w0.y, xv2);
            fma2(V2[2], w1.x, xv2); fma2(V2[3], w1.y, xv2);
            fma2(V2[4], w2.x, xv2); fma2(V2[5], w2.y, xv2);
            fma2(V2[6], w3.x, xv2); fma2(V2[7], w3.y, xv2);
        }
        const int ch = b * DMODEL + d;
        ulonglong2* vp = (ulonglong2*)(g_V4 + ((size_t)g * NCH + ch) * 4);
        vp[0] = make_ulonglong2(V2[0], V2[1]);
        vp[1] = make_ulonglong2(V2[2], V2[3]);
        vp[2] = make_ulonglong2(V2[4], V2[5]);
        vp[3] = make_ulonglong2(V2[6], V2[7]);
    }
    grid_barrier(1);

    // ================= PHASE 2: sequential prefix over segments (16 lanes/channel) ==
    if (bid < (NCH * NSTATE) / NT) {            // 256 block-jobs
        const int m  = tid & 15;
        const int ch = (bid * NT + tid) >> 4;
        float ar[NSTATE];
        #pragma unroll
        for (int n = 0; n < NSTATE; ++n) ar[n] = g_A32[m * NSTATE + n];
        const float* Vs = (const float*)g_V4;
        float*       Hs = (float*)g_H4;
        const size_t off0 = (size_t)ch * NSTATE + m;
        const size_t step = (size_t)NCH * NSTATE;
        float h = 0.f;
        float v = Vs[off0];
        size_t off = off0;
        for (int g = 0; g < NSEGS; ++g) {
            float v_next = 0.f;
            if (g < NSEGS - 1) v_next = Vs[off + step];   // prefetch next
            Hs[off] = h;
            float a0 = v, a1 = 0.f, a2 = 0.f, a3 = 0.f;
            #pragma unroll
            for (int n = 0; n < NSTATE; n += 4) {
                a0 = fmaf(ar[n + 0], __shfl_sync(0xffffffffu, h, n + 0, 16), a0);
                a1 = fmaf(ar[n + 1], __shfl_sync(0xffffffffu, h, n + 1, 16), a1);
                a2 = fmaf(ar[n + 2], __shfl_sync(0xffffffffu, h, n + 2, 16), a2);
                a3 = fmaf(ar[n + 3], __shfl_sync(0xffffffffu, h, n + 3, 16), a3);
            }
            h = (a0 + a1) + (a2 + a3);
            v = v_next;
            off += step;
        }
    }
    grid_barrier(2);

    // ================= PHASE 3: y = conv(x) + Q . H_seg  (single write) ============
    if (tid < SEG) sm.p3.sc[tid] = g_c[tid];
    if (tid < SEG * 4) ((ulonglong2*)sm.p3.sQp)[tid] = ((const ulonglong2*)g_Q4)[tid];
    for (int job = bid; job < NCH * NSEGS / NT; job += GRID) {   // 1024 jobs
        const int dt = job & 3, b = (job >> 2) & 3, g = job >> 4;
        const int d  = dt * 256 + tid;
        const int ch = b * DMODEL + d;
        const size_t base = ((size_t)(b * SEQ + g * SEG)) * DMODEL + d;
        const float* xp = x + base;

        // H loads in flight across staging + syncthreads
        const float4* hp = g_H4 + ((size_t)g * NCH + ch) * 4;
        const float4 h0 = hp[0], h1 = hp[1], h2 = hp[2], h3 = hp[3];

        __syncthreads();                        // previous job's sx consumers done
        #pragma unroll
        for (int s = 0; s < SEG; ++s) sm.p3.sx[s][tid] = xp[(size_t)s * DMODEL];
        __syncthreads();

        ull H2[8];
        H2[0] = pack2(h0.x, h0.y); H2[1] = pack2(h0.z, h0.w);
        H2[2] = pack2(h1.x, h1.y); H2[3] = pack2(h1.z, h1.w);
        H2[4] = pack2(h2.x, h2.y); H2[5] = pack2(h2.z, h2.w);
        H2[6] = pack2(h3.x, h3.y); H2[7] = pack2(h3.z, h3.w);

        float* op = out + base;
        #pragma unroll
        for (int rbase = 0; rbase < SEG; rbase += 8) {
            float acc[8];
            #pragma unroll
            for (int i = 0; i < 8; ++i) {       // acc[i] = Q[rbase+i] . H
                const ulonglong2 qa = sm.p3.sQp[rbase + i][0], qb = sm.p3.sQp[rbase + i][1];
                const ulonglong2 qc = sm.p3.sQp[rbase + i][2], qd = sm.p3.sQp[rbase + i][3];
                ull p = 0ull;
                fma2(p, qa.x, H2[0]); fma2(p, qa.y, H2[1]);
                fma2(p, qb.x, H2[2]); fma2(p, qb.y, H2[3]);
                fma2(p, qc.x, H2[4]); fma2(p, qc.y, H2[5]);
                fma2(p, qd.x, H2[6]); fma2(p, qd.y, H2[7]);
                acc[i] = unpack_add(p);
            }
            #pragma unroll
            for (int s = 0; s < SEG; ++s) {     // conv, compile-time predicates only
                if (s > rbase + 7) break;
                const float xv = sm.p3.sx[s][tid];
                #pragma unroll
                for (int i = 0; i < 8; ++i) {
                    const int k = rbase + i - s;
                    if (k >= 0 && k < SEG) acc[i] = fmaf(sm.p3.sc[k], xv, acc[i]);
                }
            }
            #pragma unroll
            for (int i = 0; i < 8; ++i) op[(size_t)(rbase + i) * DMODEL] = acc[i];
        }
    }
}

// ---------------- launch ----------------
extern "C" void kernel_launch(void* const* d_in, const int* in_sizes, int n_in,
                              void* d_out, int out_size) {
    const float* x = nullptr; const float* A = nullptr; const float* bv = nullptr;
    for (int i = 0; i < n_in; ++i) {
        if      (in_sizes[i] == BATCH * SEQ * DMODEL) x  = (const float*)d_in[i];
        else if (in_sizes[i] == NSTATE * NSTATE)      A  = (const float*)d_in[i];
        else if (in_sizes[i] == NSTATE)               bv = (const float*)d_in[i];
    }
    float* out = (float*)d_out;
    fused_all<<<GRID, NT>>>(x, A, bv, out);
}

// round 11
// speedup vs baseline: 2.8006x; 2.8006x over previous
#include <cuda_runtime.h>
#include <cuda_bf16.h>

#define BATCH  4
#define SEQ    2048
#define DMODEL 1024
#define NSTATE 16
#define SEG    32                  // segment length
#define NSEGS  (SEQ / SEG)         // 64 segments
#define NCH    (BATCH * DMODEL)    // 4096 channels

typedef unsigned long long ull;

// packed f32x2 helpers (true fp32 lanes — no precision loss)
__device__ __forceinline__ ull pack2(float lo, float hi) {
    ull r; asm("mov.b64 %0, {%1, %2};" : "=l"(r) : "f"(lo), "f"(hi)); return r;
}
__device__ __forceinline__ void fma2(ull& d, ull a, ull b) {
    asm("fma.rn.f32x2 %0, %1, %2, %0;" : "+l"(d) : "l"(a), "l"(b));
}
__device__ __forceinline__ float unpack_add(ull p) {
    float lo, hi; asm("mov.b64 {%0, %1}, %2;" : "=f"(lo), "=f"(hi) : "l"(p));
    return lo + hi;
}

// ---------------- device scratch (static: no allocation) ----------------
__device__ float  g_c[SEG];                   // c_k = b^T A^k b
__device__ float4 g_vrev4[SEG][4];            // vrev[s] = A^{SEG-1-s} b   (float4-packed)
__device__ float4 g_Q4[SEG][4];               // Q[r]  = b^T A^{r+1}      (float4-packed)
__device__ float  g_A32[NSTATE * NSTATE];     // A^SEG
__device__ float4 g_V4[NSEGS * NCH * 4];      // injected state  [g][ch][16]   (16.8 MB)
__device__ float4 g_H4[NSEGS * NCH * 4];      // entry states    [g][ch][16]   (16.8 MB)

// ---------------- K0: precompute filter taps and transition powers ----------------
__global__ void __launch_bounds__(256) k0_precompute(const float* __restrict__ A,
                                                     const float* __restrict__ bvec) {
    __shared__ float sA[NSTATE * NSTATE];
    __shared__ float M[2][NSTATE * NSTATE];
    __shared__ float sb[NSTATE];
    const int tid = threadIdx.x;            // 256 threads
    sA[tid] = A[tid];
    if (tid < NSTATE) sb[tid] = bvec[tid];
    M[0][tid] = ((tid >> 4) == (tid & 15)) ? 1.f : 0.f;   // M = I
    __syncthreads();

    float* vrev = (float*)g_vrev4;
    float* Q    = (float*)g_Q4;

    int cur = 0;
    const int row = tid >> 4, col = tid & 15;
    for (int j = 0; j < SEG; ++j) {         // at loop top: M[cur] = A^j
        if (tid < NSTATE) {                 // vrev[SEG-1-j] = A^j b
            float a = 0.f;
            #pragma unroll
            for (int n = 0; n < NSTATE; ++n) a = fmaf(M[cur][tid * NSTATE + n], sb[n], a);
            vrev[(SEG - 1 - j) * NSTATE + tid] = a;
        } else if (tid < 32 && j >= 1) {    // Q[j-1] = b^T A^j
            const int m = tid - NSTATE;
            float a = 0.f;
            #pragma unroll
            for (int k = 0; k < NSTATE; ++k) a = fmaf(sb[k], M[cur][k * NSTATE + m], a);
            Q[(j - 1) * NSTATE + m] = a;
        }
        float a = 0.f;                      // M[1-cur] = M[cur] * A
        #pragma unroll
        for (int k = 0; k < NSTATE; ++k)
            a = fmaf(M[cur][row * NSTATE + k], sA[k * NSTATE + col], a);
        M[1 - cur][tid] = a;
        __syncthreads();
        cur ^= 1;
    }
    // M[cur] = A^SEG
    g_A32[tid] = M[cur][tid];
    if (tid < NSTATE) {                     // Q[SEG-1] = b^T A^SEG
        float a = 0.f;
        #pragma unroll
        for (int k = 0; k < NSTATE; ++k) a = fmaf(sb[k], M[cur][k * NSTATE + tid], a);
        Q[(SEG - 1) * NSTATE + tid] = a;
    }
    if (tid < SEG) {                        // c_k = b . A^k b
        float a = 0.f;
        #pragma unroll
        for (int m = 0; m < NSTATE; ++m) a = fmaf(sb[m], vrev[(SEG - 1 - tid) * NSTATE + m], a);
        g_c[tid] = a;
    }
}

// ---------------- K1: injected state.  V = sum_s A^{SEG-1-s} b x_s  (packed f32x2) ----
__global__ void __launch_bounds__(256, 8) k1_inject(const float* __restrict__ x) {
    __shared__ ulonglong2 sv2[SEG][4];      // vrev rows as 8 packed f32x2 pairs each
    const int tid = threadIdx.x;
    if (tid < SEG * 4) ((ulonglong2*)sv2)[tid] = ((const ulonglong2*)g_vrev4)[tid];
    __syncthreads();

    const int job = blockIdx.x * 256 + tid;     // 262144 jobs = (ch, seg)
    const int d = job & (DMODEL - 1);
    const int b = (job >> 10) & 3;
    const int g = job >> 12;

    const float* xp = x + ((size_t)(b * SEQ + g * SEG)) * DMODEL + d;
    ull V2[8];
    #pragma unroll
    for (int j = 0; j < 8; ++j) V2[j] = 0ull;

    #pragma unroll
    for (int s = 0; s < SEG; ++s) {
        const float xv  = xp[(size_t)s * DMODEL];
        const ull   xv2 = pack2(xv, xv);
        const ulonglong2 p0 = sv2[s][0], p1 = sv2[s][1], p2 = sv2[s][2], p3 = sv2[s][3];
        fma2(V2[0], p0.x, xv2); fma2(V2[1], p0.y, xv2);
        fma2(V2[2], p1.x, xv2); fma2(V2[3], p1.y, xv2);
        fma2(V2[4], p2.x, xv2); fma2(V2[5], p2.y, xv2);
        fma2(V2[6], p3.x, xv2); fma2(V2[7], p3.y, xv2);
    }
    const int ch = b * DMODEL + d;
    ulonglong2* vp = (ulonglong2*)(g_V4 + ((size_t)g * NCH + ch) * 4);
    vp[0] = make_ulonglong2(V2[0], V2[1]);
    vp[1] = make_ulonglong2(V2[2], V2[3]);
    vp[2] = make_ulonglong2(V2[4], V2[5]);
    vp[3] = make_ulonglong2(V2[6], V2[7]);
}

// ---------------- K2: fused sequential prefix over segments ----------------
// 16 lanes per channel (lane = state dim m). H_{g+1} = A32 H_g + V_g; store entry states.
__global__ void __launch_bounds__(256) k2_prefix(void) {
    const int tid = threadIdx.x;
    const int m   = tid & 15;
    const int ch  = (blockIdx.x * 256 + tid) >> 4;     // 256 blocks -> 4096 channels

    float ar[NSTATE];
    #pragma unroll
    for (int n = 0; n < NSTATE; ++n) ar[n] = g_A32[m * NSTATE + n];

    const float* Vs = (const float*)g_V4;
    float*       Hs = (float*)g_H4;
    const size_t off0 = (size_t)ch * NSTATE + m;
    const size_t step = (size_t)NCH * NSTATE;

    float h = 0.f;
    float v = Vs[off0];                                // prefetch g=0
    size_t off = off0;
    for (int g = 0; g < NSEGS; ++g) {
        float v_next = 0.f;
        if (g < NSEGS - 1) v_next = Vs[off + step];    // prefetch next (hides L2 latency)
        Hs[off] = h;                                   // entry state of segment g
        float a0 = v, a1 = 0.f, a2 = 0.f, a3 = 0.f;
        #pragma unroll
        for (int n = 0; n < NSTATE; n += 4) {
            a0 = fmaf(ar[n + 0], __shfl_sync(0xffffffffu, h, n + 0, 16), a0);
            a1 = fmaf(ar[n + 1], __shfl_sync(0xffffffffu, h, n + 1, 16), a1);
            a2 = fmaf(ar[n + 2], __shfl_sync(0xffffffffu, h, n + 2, 16), a2);
            a3 = fmaf(ar[n + 3], __shfl_sync(0xffffffffu, h, n + 3, 16), a3);
        }
        h = (a0 + a1) + (a2 + a3);
        v = v_next;
        off += step;
    }
}

// ---------------- K3: y = conv(x) + Q . H_seg.  x staged in SMEM, 4x8-output passes --
// (256,5): 51-reg cap — enough for the acc[8] body (R8's 40-reg cap spilled; R7's
//  64-reg version left occupancy at 4 blocks/SM).
__global__ void __launch_bounds__(256, 5) k3_fused(const float* __restrict__ x,
                                                   float* __restrict__ out) {
    __shared__ float      sx[SEG][256];     // 32 KB x tile, read once from DRAM
    __shared__ float      sc[SEG];
    __shared__ ulonglong2 sQp[SEG][4];      // Q rows as packed f32x2 pairs
    const int tid = threadIdx.x;
    if (tid < SEG) sc[tid] = g_c[tid];
    if (tid < SEG * 4) ((ulonglong2*)sQp)[tid] = ((const ulonglong2*)g_Q4)[tid];

    const int bid = blockIdx.x;             // 1024 blocks = 4 dtiles * 4 batch * 64 segs
    const int dt  = bid & 3;
    const int b   = (bid >> 2) & 3;
    const int g   = bid >> 4;
    const int d   = dt * 256 + tid;
    const int ch  = b * DMODEL + d;

    // H loads issued first: in flight across staging + syncthreads
    const float4* hp = g_H4 + ((size_t)g * NCH + ch) * 4;
    const float4 h0 = hp[0], h1 = hp[1], h2 = hp[2], h3 = hp[3];

    const size_t base = ((size_t)(b * SEQ + g * SEG)) * DMODEL + d;
    const float* xp = x + base;
    #pragma unroll
    for (int s = 0; s < SEG; ++s) sx[s][tid] = xp[(size_t)s * DMODEL];
    __syncthreads();

    ull H2[8];
    H2[0] = pack2(h0.x, h0.y); H2[1] = pack2(h0.z, h0.w);
    H2[2] = pack2(h1.x, h1.y); H2[3] = pack2(h1.z, h1.w);
    H2[4] = pack2(h2.x, h2.y); H2[5] = pack2(h2.z, h2.w);
    H2[6] = pack2(h3.x, h3.y); H2[7] = pack2(h3.z, h3.w);

    float* op = out + base;

    #pragma unroll
    for (int rbase = 0; rbase < SEG; rbase += 8) {
        float acc[8];
        // acc[i] = Q[rbase+i] . H   (packed: 8 fma2 per output)
        #pragma unroll
        for (int i = 0; i < 8; ++i) {
            const ulonglong2 qa = sQp[rbase + i][0], qb = sQp[rbase + i][1];
            const ulonglong2 qc = sQp[rbase + i][2], qd = sQp[rbase + i][3];
            ull p = 0ull;
            fma2(p, qa.x, H2[0]); fma2(p, qa.y, H2[1]);
            fma2(p, qb.x, H2[2]); fma2(p, qb.y, H2[3]);
            fma2(p, qc.x, H2[4]); fma2(p, qc.y, H2[5]);
            fma2(p, qd.x, H2[6]); fma2(p, qd.y, H2[7]);
            acc[i] = unpack_add(p);
        }
        // conv: acc[i] += sum_s c[rbase+i-s] * x[s]; compile-time predicates only
        #pragma unroll
        for (int s = 0; s < SEG; ++s) {
            if (s > rbase + 7) break;
            const float xv = sx[s][tid];
            #pragma unroll
            for (int i = 0; i < 8; ++i) {
                const int k = rbase + i - s;
                if (k >= 0 && k < SEG) acc[i] = fmaf(sc[k], xv, acc[i]);
            }
        }
        #pragma unroll
        for (int i = 0; i < 8; ++i) op[(size_t)(rbase + i) * DMODEL] = acc[i];
    }
}

// ---------------- launch ----------------
extern "C" void kernel_launch(void* const* d_in, const int* in_sizes, int n_in,
                              void* d_out, int out_size) {
    const float* x = nullptr; const float* A = nullptr; const float* bv = nullptr;
    for (int i = 0; i < n_in; ++i) {
        if      (in_sizes[i] == BATCH * SEQ * DMODEL) x  = (const float*)d_in[i];
        else if (in_sizes[i] == NSTATE * NSTATE)      A  = (const float*)d_in[i];
        else if (in_sizes[i] == NSTATE)               bv = (const float*)d_in[i];
    }
    float* out = (float*)d_out;

    k0_precompute<<<1, 256>>>(A, bv);
    k1_inject<<<(NCH * NSEGS) / 256, 256>>>(x);              // 1024 blocks
    k2_prefix<<<(NCH * NSTATE) / 256, 256>>>();              // 256 blocks
    k3_fused<<<(NCH * NSEGS) / 256, 256>>>(x, out);          // 1024 blocks
}

// round 12
// speedup vs baseline: 2.9850x; 1.0659x over previous
#include <cuda_runtime.h>
#include <cuda_bf16.h>

#define BATCH  4
#define SEQ    2048
#define DMODEL 1024
#define NSTATE 16
#define SEG    32                  // segment length
#define NSEGS  (SEQ / SEG)         // 64 segments
#define NCH    (BATCH * DMODEL)    // 4096 channels

typedef unsigned long long ull;

// packed f32x2 helpers (true fp32 lanes — no precision loss)
__device__ __forceinline__ ull pack2(float lo, float hi) {
    ull r; asm("mov.b64 %0, {%1, %2};" : "=l"(r) : "f"(lo), "f"(hi)); return r;
}
__device__ __forceinline__ void fma2(ull& d, ull a, ull b) {
    asm("fma.rn.f32x2 %0, %1, %2, %0;" : "+l"(d) : "l"(a), "l"(b));
}
__device__ __forceinline__ float unpack_add(ull p) {
    float lo, hi; asm("mov.b64 {%0, %1}, %2;" : "=f"(lo), "=f"(hi) : "l"(p));
    return lo + hi;
}

// ---------------- device scratch (static: no allocation) ----------------
__device__ float  g_c[SEG];                   // c_k = b^T A^k b
__device__ float4 g_vrev4[SEG][4];            // vrev[s] = A^{SEG-1-s} b   (float4-packed)
__device__ float4 g_Q4[SEG][4];               // Q[r]  = b^T A^{r+1}      (float4-packed)
__device__ float  g_A32[NSTATE * NSTATE];     // A^SEG
__device__ float4 g_V4[NSEGS * NCH * 4];      // injected state  [g][ch][16]   (16.8 MB)
__device__ float4 g_H4[NSEGS * NCH * 4];      // entry states    [g][ch][16]   (16.8 MB)

// ---------------- K0: precompute filter taps and transition powers ----------------
__global__ void __launch_bounds__(256) k0_precompute(const float* __restrict__ A,
                                                     const float* __restrict__ bvec) {
    __shared__ float sA[NSTATE * NSTATE];
    __shared__ float M[2][NSTATE * NSTATE];
    __shared__ float sb[NSTATE];
    const int tid = threadIdx.x;            // 256 threads
    sA[tid] = A[tid];
    if (tid < NSTATE) sb[tid] = bvec[tid];
    M[0][tid] = ((tid >> 4) == (tid & 15)) ? 1.f : 0.f;   // M = I
    __syncthreads();

    float* vrev = (float*)g_vrev4;
    float* Q    = (float*)g_Q4;

    int cur = 0;
    const int row = tid >> 4, col = tid & 15;
    for (int j = 0; j < SEG; ++j) {         // at loop top: M[cur] = A^j
        if (tid < NSTATE) {                 // vrev[SEG-1-j] = A^j b
            float a = 0.f;
            #pragma unroll
            for (int n = 0; n < NSTATE; ++n) a = fmaf(M[cur][tid * NSTATE + n], sb[n], a);
            vrev[(SEG - 1 - j) * NSTATE + tid] = a;
        } else if (tid < 32 && j >= 1) {    // Q[j-1] = b^T A^j
            const int m = tid - NSTATE;
            float a = 0.f;
            #pragma unroll
            for (int k = 0; k < NSTATE; ++k) a = fmaf(sb[k], M[cur][k * NSTATE + m], a);
            Q[(j - 1) * NSTATE + m] = a;
        }
        float a = 0.f;                      // M[1-cur] = M[cur] * A
        #pragma unroll
        for (int k = 0; k < NSTATE; ++k)
            a = fmaf(M[cur][row * NSTATE + k], sA[k * NSTATE + col], a);
        M[1 - cur][tid] = a;
        __syncthreads();
        cur ^= 1;
    }
    // M[cur] = A^SEG
    g_A32[tid] = M[cur][tid];
    if (tid < NSTATE) {                     // Q[SEG-1] = b^T A^SEG
        float a = 0.f;
        #pragma unroll
        for (int k = 0; k < NSTATE; ++k) a = fmaf(sb[k], M[cur][k * NSTATE + tid], a);
        Q[(SEG - 1) * NSTATE + tid] = a;
    }
    if (tid < SEG) {                        // c_k = b . A^k b
        float a = 0.f;
        #pragma unroll
        for (int m = 0; m < NSTATE; ++m) a = fmaf(sb[m], vrev[(SEG - 1 - tid) * NSTATE + m], a);
        g_c[tid] = a;
    }
}

// ---------------- K1: injected state.  V = sum_s A^{SEG-1-s} b x_s  (packed f32x2) ----
// (256,6): 42-reg budget — body needs ~38 live regs; the old (256,8)=32-reg cap
//  likely spilled (never directly profiled; fix based on R8/R11 spill signatures).
__global__ void __launch_bounds__(256, 6) k1_inject(const float* __restrict__ x) {
    __shared__ ulonglong2 sv2[SEG][4];      // vrev rows as 8 packed f32x2 pairs each
    const int tid = threadIdx.x;
    if (tid < SEG * 4) ((ulonglong2*)sv2)[tid] = ((const ulonglong2*)g_vrev4)[tid];
    __syncthreads();

    const int job = blockIdx.x * 256 + tid;     // 262144 jobs = (ch, seg)
    const int d = job & (DMODEL - 1);
    const int b = (job >> 10) & 3;
    const int g = job >> 12;

    const float* xp = x + ((size_t)(b * SEQ + g * SEG)) * DMODEL + d;
    ull V2[8];
    #pragma unroll
    for (int j = 0; j < 8; ++j) V2[j] = 0ull;

    #pragma unroll
    for (int s = 0; s < SEG; ++s) {
        const float xv  = xp[(size_t)s * DMODEL];
        const ull   xv2 = pack2(xv, xv);
        const ulonglong2 p0 = sv2[s][0], p1 = sv2[s][1], p2 = sv2[s][2], p3 = sv2[s][3];
        fma2(V2[0], p0.x, xv2); fma2(V2[1], p0.y, xv2);
        fma2(V2[2], p1.x, xv2); fma2(V2[3], p1.y, xv2);
        fma2(V2[4], p2.x, xv2); fma2(V2[5], p2.y, xv2);
        fma2(V2[6], p3.x, xv2); fma2(V2[7], p3.y, xv2);
    }
    const int ch = b * DMODEL + d;
    ulonglong2* vp = (ulonglong2*)(g_V4 + ((size_t)g * NCH + ch) * 4);
    vp[0] = make_ulonglong2(V2[0], V2[1]);
    vp[1] = make_ulonglong2(V2[2], V2[3]);
    vp[2] = make_ulonglong2(V2[4], V2[5]);
    vp[3] = make_ulonglong2(V2[6], V2[7]);
}

// ---------------- K2: fused sequential prefix over segments ----------------
// 16 lanes per channel (lane = state dim m). H_{g+1} = A32 H_g + V_g; store entry states.
__global__ void __launch_bounds__(256) k2_prefix(void) {
    const int tid = threadIdx.x;
    const int m   = tid & 15;
    const int ch  = (blockIdx.x * 256 + tid) >> 4;     // 256 blocks -> 4096 channels

    float ar[NSTATE];
    #pragma unroll
    for (int n = 0; n < NSTATE; ++n) ar[n] = g_A32[m * NSTATE + n];

    const float* Vs = (const float*)g_V4;
    float*       Hs = (float*)g_H4;
    const size_t off0 = (size_t)ch * NSTATE + m;
    const size_t step = (size_t)NCH * NSTATE;

    float h = 0.f;
    float v = Vs[off0];                                // prefetch g=0
    size_t off = off0;
    for (int g = 0; g < NSEGS; ++g) {
        float v_next = 0.f;
        if (g < NSEGS - 1) v_next = Vs[off + step];    // prefetch next (hides L2 latency)
        Hs[off] = h;                                   // entry state of segment g
        float a0 = v, a1 = 0.f, a2 = 0.f, a3 = 0.f;
        #pragma unroll
        for (int n = 0; n < NSTATE; n += 4) {
            a0 = fmaf(ar[n + 0], __shfl_sync(0xffffffffu, h, n + 0, 16), a0);
            a1 = fmaf(ar[n + 1], __shfl_sync(0xffffffffu, h, n + 1, 16), a1);
            a2 = fmaf(ar[n + 2], __shfl_sync(0xffffffffu, h, n + 2, 16), a2);
            a3 = fmaf(ar[n + 3], __shfl_sync(0xffffffffu, h, n + 3, 16), a3);
        }
        h = (a0 + a1) + (a2 + a3);
        v = v_next;
        off += step;
    }
}

// ---------------- K3: y = conv(x) + Q . H_seg.  x staged in SMEM (R7 exact: 23.0us) --
// (256,4): 64-reg budget. Measured curve: 64r/occ41% = 23.0us; 48r = 32.8; 40r = 59.7.
__global__ void __launch_bounds__(256, 4) k3_fused(const float* __restrict__ x,
                                                   float* __restrict__ out) {
    __shared__ float      sx[SEG][256];     // 32 KB x tile, read once from DRAM
    __shared__ float      sc[SEG];
    __shared__ ulonglong2 sQp[SEG][4];      // Q rows as packed f32x2 pairs
    const int tid = threadIdx.x;
    if (tid < SEG) sc[tid] = g_c[tid];
    if (tid < SEG * 4) ((ulonglong2*)sQp)[tid] = ((const ulonglong2*)g_Q4)[tid];

    const int bid = blockIdx.x;             // 1024 blocks = 4 dtiles * 4 batch * 64 segs
    const int dt  = bid & 3;
    const int b   = (bid >> 2) & 3;
    const int g   = bid >> 4;
    const int d   = dt * 256 + tid;
    const int ch  = b * DMODEL + d;

    // H loads issued first: in flight across staging + syncthreads
    const float4* hp = g_H4 + ((size_t)g * NCH + ch) * 4;
    const float4 h0 = hp[0], h1 = hp[1], h2 = hp[2], h3 = hp[3];

    const size_t base = ((size_t)(b * SEQ + g * SEG)) * DMODEL + d;
    const float* xp = x + base;
    #pragma unroll
    for (int s = 0; s < SEG; ++s) sx[s][tid] = xp[(size_t)s * DMODEL];
    __syncthreads();

    ull H2[8];
    H2[0] = pack2(h0.x, h0.y); H2[1] = pack2(h0.z, h0.w);
    H2[2] = pack2(h1.x, h1.y); H2[3] = pack2(h1.z, h1.w);
    H2[4] = pack2(h2.x, h2.y); H2[5] = pack2(h2.z, h2.w);
    H2[6] = pack2(h3.x, h3.y); H2[7] = pack2(h3.z, h3.w);

    float* op = out + base;

    #pragma unroll
    for (int rbase = 0; rbase < SEG; rbase += 8) {
        float acc[8];
        // acc[i] = Q[rbase+i] . H   (packed: 8 fma2 per output)
        #pragma unroll
        for (int i = 0; i < 8; ++i) {
            const ulonglong2 qa = sQp[rbase + i][0], qb = sQp[rbase + i][1];
            const ulonglong2 qc = sQp[rbase + i][2], qd = sQp[rbase + i][3];
            ull p = 0ull;
            fma2(p, qa.x, H2[0]); fma2(p, qa.y, H2[1]);
            fma2(p, qb.x, H2[2]); fma2(p, qb.y, H2[3]);
            fma2(p, qc.x, H2[4]); fma2(p, qc.y, H2[5]);
            fma2(p, qd.x, H2[6]); fma2(p, qd.y, H2[7]);
            acc[i] = unpack_add(p);
        }
        // conv: acc[i] += sum_s c[rbase+i-s] * x[s]; compile-time predicates only
        #pragma unroll
        for (int s = 0; s < SEG; ++s) {
            if (s > rbase + 7) break;
            const float xv = sx[s][tid];
            #pragma unroll
            for (int i = 0; i < 8; ++i) {
                const int k = rbase + i - s;
                if (k >= 0 && k < SEG) acc[i] = fmaf(sc[k], xv, acc[i]);
            }
        }
        #pragma unroll
        for (int i = 0; i < 8; ++i) op[(size_t)(rbase + i) * DMODEL] = acc[i];
    }
}

// ---------------- launch ----------------
extern "C" void kernel_launch(void* const* d_in, const int* in_sizes, int n_in,
                              void* d_out, int out_size) {
    const float* x = nullptr; const float* A = nullptr; const float* bv = nullptr;
    for (int i = 0; i < n_in; ++i) {
        if      (in_sizes[i] == BATCH * SEQ * DMODEL) x  = (const float*)d_in[i];
        else if (in_sizes[i] == NSTATE * NSTATE)      A  = (const float*)d_in[i];
        else if (in_sizes[i] == NSTATE)               bv = (const float*)d_in[i];
    }
    float* out = (float*)d_out;

    k0_precompute<<<1, 256>>>(A, bv);
    k1_inject<<<(NCH * NSEGS) / 256, 256>>>(x);              // 1024 blocks
    k2_prefix<<<(NCH * NSTATE) / 256, 256>>>();              // 256 blocks
    k3_fused<<<(NCH * NSEGS) / 256, 256>>>(x, out);          // 1024 blocks
}